// round 1
// baseline (speedup 1.0000x reference)
#include <cuda_runtime.h>
#include <math.h>

// Problem constants
#define SEGS     512
#define MAXD     512
#define NUM_POS  8
#define WDIM     512
#define HDIM     512
#define BATCH    16
#define CHAN     3
#define NW       1025          // SEGS*(N-1)+1
#define SW_STRIDE 1026         // pad so each table base is 8B-aligned

struct PosConsts {
    float Cx[NUM_POS];
    float Cy[NUM_POS];
    float D [NUM_POS];
};

// One block = fixed channel c, 256 pixels. Each thread owns one pixel and
// loops over the 16 batch images, reusing the 8 affine position terms P[i].
__global__ __launch_bounds__(256)
void stripe_poly_kernel(const float* __restrict__ x,
                        const float* __restrict__ wts,
                        float* __restrict__ out,
                        PosConsts pc)
{
    __shared__ float sw[NUM_POS * SW_STRIDE];

    const int c = blockIdx.y;

    // Stage this channel's 8 weight tables (8 x 1025 floats = 32.8 KB)
    for (int idx = threadIdx.x; idx < NUM_POS * NW; idx += 256) {
        int i = idx / NW;
        int j = idx - i * NW;
        sw[i * SW_STRIDE + j] = wts[(i * CHAN + c) * NW + j];
    }
    __syncthreads();

    const int pixel = blockIdx.x * 256 + threadIdx.x;   // grid.x*256 == 512*512
    const float wx = (float)(pixel >> 9);
    const float hy = (float)(pixel & 511);

    // xs = 0.5*x + P[i],  P[i] = Cx*w + Cy*h + D  (folded position encode)
    float P[NUM_POS];
#pragma unroll
    for (int i = 0; i < NUM_POS; i++)
        P[i] = fmaf(pc.Cx[i], wx, fmaf(pc.Cy[i], hy, pc.D[i]));

#pragma unroll 1
    for (int b = 0; b < BATCH; b++) {
        const int eidx = ((b * CHAN + c) << 18) + pixel;  // 512*512 = 1<<18
        const float xv = x[eidx];
        float acc = 0.f;
#pragma unroll
        for (int i = 0; i < NUM_POS; i++) {
            float xs = fmaf(0.5f, xv, P[i]);
            float sf = floorf(xs);
            sf = fminf(fmaxf(sf, 0.f), 511.f);
            float t  = fmaf(2.f, xs - sf, -1.f);          // local coord in [-1,1]
            int  sid = (int)sf;
            const float* wp = sw + i * SW_STRIDE + 2 * sid;
            float2 w01 = *(const float2*)wp;              // weights sid*2, sid*2+1
            float  w2  = wp[2];
            // value = w1 + 0.5*t*((w2-w0) + t*(w0+w2-2*w1))
            float e  = fmaf(-2.f, w01.y, w01.x + w2);
            float dd = w2 - w01.x;
            acc += fmaf(0.5f * t, fmaf(t, e, dd), w01.y);
        }
        out[eidx] = acc * 0.125f;
    }
}

extern "C" void kernel_launch(void* const* d_in, const int* in_sizes, int n_in,
                              void* d_out, int out_size)
{
    const float* x   = (const float*)d_in[0];   // [16, 3, 512, 512]
    const float* wts = (const float*)d_in[1];   // [8, 3, 1025]
    float* out = (float*)d_out;

    // Fold position maps analytically (double precision on host):
    //   r = cx*w + sgn*cy*h ; rmin/rmax at grid corners (cx,cy >= 0)
    //   pos = (r - rmin)*RATIO/dr*512 - 256
    //   xs  = 0.5*x + pos + 256 = 0.5*x + (r - rmin)*S,  S = RATIO*512/dr
    PosConsts pc;
    const double RATIO = (double)MAXD / (double)(MAXD + 1);
    for (int rot = 0; rot < 4; rot++) {
        double theta = (M_PI / 2.0) * ((double)rot / 4.0);
        double cx = cos(theta), cy = sin(theta);
        for (int s = 0; s < 2; s++) {
            double sgn  = (s == 0) ? 1.0 : -1.0;
            double rmin = (s == 0) ? 0.0 : -cy * (HDIM - 1);
            double rmax = (s == 0) ? (cx + cy) * (WDIM - 1) : cx * (WDIM - 1);
            double dr   = rmax - rmin;
            double S    = RATIO * (double)MAXD / dr;
            int p = rot * 2 + s;
            pc.Cx[p] = (float)(cx * S);
            pc.Cy[p] = (float)(sgn * cy * S);
            pc.D [p] = (float)(-rmin * S);
        }
    }

    dim3 grid(WDIM * HDIM / 256, CHAN, 1);   // (1024, 3)
    stripe_poly_kernel<<<grid, 256>>>(x, wts, out, pc);
}

// round 2
// speedup vs baseline: 1.1944x; 1.1944x over previous
#include <cuda_runtime.h>
#include <math.h>

#define SEGS     512
#define MAXD     512
#define NUM_POS  8
#define WDIM     512
#define HDIM     512
#define BATCH    16
#define CHAN     3
#define NW       1025

struct PosConsts {
    float Cx[NUM_POS];
    float Cy[NUM_POS];
    float D [NUM_POS];
};

// Precomputed per-segment quadratic coefficients, laid out [pos][chan][seg].
// val(u) = C + u*(B + u*A), u = xs - sid, 0.125 (1/NUM_POS) folded in.
__device__ float4 g_coef[NUM_POS * CHAN * SEGS];

__global__ __launch_bounds__(256)
void prep_coef_kernel(const float* __restrict__ wts)
{
    int idx = blockIdx.x * 256 + threadIdx.x;          // [0, 8*3*512)
    if (idx >= NUM_POS * CHAN * SEGS) return;
    int s  = idx & (SEGS - 1);
    int ic = idx >> 9;                                  // i*CHAN + c
    const float* w = wts + ic * NW + 2 * s;
    float w0 = w[0], w1 = w[1], w2 = w[2];
    float A = 0.125f * (2.f * (w0 + w2) - 4.f * w1);
    float B = 0.125f * (4.f * w1 - 3.f * w0 - w2);
    float C = 0.125f * w0;
    g_coef[idx] = make_float4(A, B, C, 0.f);
}

__global__ __launch_bounds__(512, 3)
void stripe_poly_kernel(const float* __restrict__ x,
                        float* __restrict__ out,
                        PosConsts pc)
{
    extern __shared__ float4 scoef[];                   // [8][512] = 64 KB

    const int c = blockIdx.y;

    // Stage this channel's 8 coefficient tables
    for (int k = threadIdx.x; k < NUM_POS * SEGS; k += 512) {
        int i = k >> 9;
        int s = k & (SEGS - 1);
        scoef[k] = g_coef[(i * CHAN + c) * SEGS + s];
    }
    __syncthreads();

    const int pixel = blockIdx.x * 512 + threadIdx.x;   // grid.x*512 == 512*512
    const float wx = (float)(pixel >> 9);
    const float hy = (float)(pixel & 511);

    float P[NUM_POS];
#pragma unroll
    for (int i = 0; i < NUM_POS; i++)
        P[i] = fmaf(pc.Cx[i], wx, fmaf(pc.Cy[i], hy, pc.D[i]));

#pragma unroll 1
    for (int b = 0; b < BATCH; b++) {
        const int eidx = ((b * CHAN + c) << 18) + pixel;
        const float xv = x[eidx];
        float acc;

        // positions 0 and 1 share an identical position map (theta=0)
        {
            float xs = fmaf(0.5f, xv, P[0]);
            float sf = fminf(fmaxf(floorf(xs), 0.f), 511.f);
            float u  = xs - sf;
            int sid  = (int)sf;
            float4 k0 = scoef[sid];
            float4 k1 = scoef[SEGS + sid];
            acc  = fmaf(u, fmaf(u, k0.x, k0.y), k0.z);
            acc += fmaf(u, fmaf(u, k1.x, k1.y), k1.z);
        }
#pragma unroll
        for (int i = 2; i < NUM_POS; i++) {
            float xs = fmaf(0.5f, xv, P[i]);
            float sf = fminf(fmaxf(floorf(xs), 0.f), 511.f);
            float u  = xs - sf;
            int sid  = (int)sf;
            float4 kk = scoef[i * SEGS + sid];
            acc += fmaf(u, fmaf(u, kk.x, kk.y), kk.z);
        }
        out[eidx] = acc;
    }
}

extern "C" void kernel_launch(void* const* d_in, const int* in_sizes, int n_in,
                              void* d_out, int out_size)
{
    const float* x   = (const float*)d_in[0];   // [16, 3, 512, 512]
    const float* wts = (const float*)d_in[1];   // [8, 3, 1025]
    float* out = (float*)d_out;

    // Fold position maps analytically (host, double precision):
    //   xs = 0.5*x + (r - rmin) * S,  S = RATIO*512/dr,  r = cx*w + sgn*cy*h
    PosConsts pc;
    const double RATIO = (double)MAXD / (double)(MAXD + 1);
    for (int rot = 0; rot < 4; rot++) {
        double theta = (M_PI / 2.0) * ((double)rot / 4.0);
        double cx = cos(theta), cy = sin(theta);
        for (int s = 0; s < 2; s++) {
            double sgn  = (s == 0) ? 1.0 : -1.0;
            double rmin = (s == 0) ? 0.0 : -cy * (HDIM - 1);
            double rmax = (s == 0) ? (cx + cy) * (WDIM - 1) : cx * (WDIM - 1);
            double dr   = rmax - rmin;
            double S    = RATIO * (double)MAXD / dr;
            int p = rot * 2 + s;
            pc.Cx[p] = (float)(cx * S);
            pc.Cy[p] = (float)(sgn * cy * S);
            pc.D [p] = (float)(-rmin * S);
        }
    }

    prep_coef_kernel<<<(NUM_POS * CHAN * SEGS + 255) / 256, 256>>>(wts);

    const int smem = NUM_POS * SEGS * sizeof(float4);   // 64 KB
    cudaFuncSetAttribute(stripe_poly_kernel,
                         cudaFuncAttributeMaxDynamicSharedMemorySize, smem);
    dim3 grid(WDIM * HDIM / 512, CHAN, 1);              // (512, 3)
    stripe_poly_kernel<<<grid, 512, smem>>>(x, out, pc);
}

// round 3
// speedup vs baseline: 1.3849x; 1.1595x over previous
#include <cuda_runtime.h>
#include <math.h>

#define SEGS     512
#define MAXD     512
#define NUM_POS  8
#define NTBL     7            // pos 0+1 share a map -> pre-summed into table 0
#define WDIM     512
#define HDIM     512
#define BATCH    16
#define CHAN     3
#define NW       1025

struct PosConsts {
    float Cx[NTBL];
    float Cy[NTBL];
    float D [NTBL];
};

// Per-segment quadratic coefficients: val(u) = C + u*(B + u*A), u = xs - sid,
// 1/NUM_POS folded in. SoA: (A,B) pairs and C separately, [chan][tbl][seg].
__device__ float2 g_AB[CHAN * NTBL * SEGS];
__device__ float  g_C [CHAN * NTBL * SEGS];

__device__ __forceinline__ void coef_from_w(const float* w, float& A, float& B, float& C)
{
    float w0 = w[0], w1 = w[1], w2 = w[2];
    A = 0.125f * (2.f * (w0 + w2) - 4.f * w1);
    B = 0.125f * (4.f * w1 - 3.f * w0 - w2);
    C = 0.125f * w0;
}

__global__ __launch_bounds__(256)
void prep_coef_kernel(const float* __restrict__ wts)
{
    int idx = blockIdx.x * 256 + threadIdx.x;           // [0, 3*7*512)
    if (idx >= CHAN * NTBL * SEGS) return;
    int s   = idx & (SEGS - 1);
    int ct  = idx >> 9;
    int c   = ct / NTBL;
    int tbl = ct - c * NTBL;

    float A, B, C;
    if (tbl == 0) {
        float A0, B0, C0, A1, B1, C1;
        coef_from_w(wts + (0 * CHAN + c) * NW + 2 * s, A0, B0, C0);
        coef_from_w(wts + (1 * CHAN + c) * NW + 2 * s, A1, B1, C1);
        A = A0 + A1; B = B0 + B1; C = C0 + C1;
    } else {
        int pos = tbl + 1;                              // 2..7
        coef_from_w(wts + (pos * CHAN + c) * NW + 2 * s, A, B, C);
    }
    int o = (c * NTBL + tbl) * SEGS + s;
    g_AB[o] = make_float2(A, B);
    g_C [o] = C;
}

__global__ __launch_bounds__(512, 3)
void stripe_poly_kernel(const float* __restrict__ x,
                        float* __restrict__ out,
                        PosConsts pc)
{
    __shared__ float2 sAB[NTBL * SEGS];                 // 28 KB
    __shared__ float  sC [NTBL * SEGS];                 // 14 KB

    const int c = blockIdx.y;

    for (int k = threadIdx.x; k < NTBL * SEGS; k += 512) {
        int o = c * NTBL * SEGS + k;
        sAB[k] = g_AB[o];
        sC [k] = g_C [o];
    }
    __syncthreads();

    const int pixel = blockIdx.x * 512 + threadIdx.x;   // grid.x*512 == 512*512
    const float wx = (float)(pixel >> 9);
    const float hy = (float)(pixel & 511);

    float P[NTBL];
#pragma unroll
    for (int i = 0; i < NTBL; i++)
        P[i] = fmaf(pc.Cx[i], wx, fmaf(pc.Cy[i], hy, pc.D[i]));

#pragma unroll 2
    for (int b = 0; b < BATCH; b++) {
        const int eidx = ((b * CHAN + c) << 18) + pixel;
        const float xv = x[eidx];
        float acc = 0.f;
#pragma unroll
        for (int i = 0; i < NTBL; i++) {
            float xs = fmaf(0.5f, xv, P[i]);
            float sf = fminf(fmaxf(floorf(xs), 0.f), 511.f);
            float u  = xs - sf;
            int sid  = i * SEGS + (int)sf;
            float2 ab = sAB[sid];
            float  cc = sC [sid];
            acc = fmaf(u, fmaf(u, ab.x, ab.y), acc + cc);
        }
        out[eidx] = acc;
    }
}

extern "C" void kernel_launch(void* const* d_in, const int* in_sizes, int n_in,
                              void* d_out, int out_size)
{
    const float* x   = (const float*)d_in[0];   // [16, 3, 512, 512]
    const float* wts = (const float*)d_in[1];   // [8, 3, 1025]
    float* out = (float*)d_out;

    // Fold position maps analytically (host, double precision):
    //   xs = 0.5*x + (r - rmin) * S,  S = RATIO*512/dr,  r = cx*w + sgn*cy*h
    PosConsts pc;
    const double RATIO = (double)MAXD / (double)(MAXD + 1);
    for (int rot = 0; rot < 4; rot++) {
        double theta = (M_PI / 2.0) * ((double)rot / 4.0);
        double cx = cos(theta), cy = sin(theta);
        for (int s = 0; s < 2; s++) {
            int pos = rot * 2 + s;
            int tbl = (pos <= 1) ? 0 : pos - 1;         // pos 0,1 -> table 0
            double sgn  = (s == 0) ? 1.0 : -1.0;
            double rmin = (s == 0) ? 0.0 : -cy * (HDIM - 1);
            double rmax = (s == 0) ? (cx + cy) * (WDIM - 1) : cx * (WDIM - 1);
            double dr   = rmax - rmin;
            double S    = RATIO * (double)MAXD / dr;
            pc.Cx[tbl] = (float)(cx * S);
            pc.Cy[tbl] = (float)(sgn * cy * S);
            pc.D [tbl] = (float)(-rmin * S);
        }
    }

    prep_coef_kernel<<<(CHAN * NTBL * SEGS + 255) / 256, 256>>>(wts);

    dim3 grid(WDIM * HDIM / 512, CHAN, 1);              // (512, 3)
    stripe_poly_kernel<<<grid, 512>>>(x, out, pc);
}